// round 6
// baseline (speedup 1.0000x reference)
#include <cuda_runtime.h>
#include <cuda_bf16.h>
#include <cstdint>

// Problem dims (fixed by the reference)
#define T_STEPS 512
#define BATCH   64
#define IDIM    256
#define HDIM    512
#define ODIM    64
#define G3      (3*HDIM)   // 1536

// ---------------- device scratch (no allocations allowed) ----------------
__device__ float    g_xproj[(size_t)T_STEPS * BATCH * G3];    // x @ x2h_w^T + b
__device__ float    g_rnn  [(size_t)T_STEPS * BATCH * HDIM];  // fallback rnn buffer
__device__ float    g_hbuf [2 * BATCH * HDIM];                // double-buffered h
__device__ unsigned g_flags[128];                             // per-CTA barrier flags

// ---------------- tf32 helpers ----------------
__device__ __forceinline__ unsigned f2tf32(float x) {
    unsigned r;
    asm("cvt.rna.tf32.f32 %0, %1;" : "=r"(r) : "f"(x));
    return r;
}
__device__ __forceinline__ float f2tf32f(float x) { return __uint_as_float(f2tf32(x)); }

__device__ __forceinline__ void mma_tf32(float* c,
                                         unsigned a0, unsigned a1, unsigned a2, unsigned a3,
                                         unsigned b0, unsigned b1) {
    asm volatile(
        "mma.sync.aligned.m16n8k8.row.col.f32.tf32.tf32.f32 "
        "{%0,%1,%2,%3}, {%4,%5,%6,%7}, {%8,%9}, {%0,%1,%2,%3};\n"
        : "+f"(c[0]), "+f"(c[1]), "+f"(c[2]), "+f"(c[3])
        : "r"(a0), "r"(a1), "r"(a2), "r"(a3), "r"(b0), "r"(b1));
}

// ---------------- tf32 GEMM with register double-buffer prefetch ----------------
// C[M,N] = A[M,K] * B[N,K]^T + bias.  RNA tf32 rounding applied on SMEM store.
template <int BM, int BN, int BK, int WGM, int WGN>
__global__ void __launch_bounds__(WGM * WGN * 32)
gemm_tf32_nt(const float* __restrict__ A, const float* __restrict__ Bw,
             const float* __restrict__ bias, float* __restrict__ C,
             int M, int N, int K)
{
    constexpr int THREADS = WGM * WGN * 32;
    constexpr int MT = BM / (WGM * 16);
    constexpr int NT = BN / (WGN * 8);
    constexpr int LDA = BK + 4;                    // padded: conflict-free loads
    constexpr int AV = (BM * (BK / 4)) / THREADS;  // float4 per thread (A tile)
    constexpr int BV = (BN * (BK / 4)) / THREADS;  // float4 per thread (B tile)

    __shared__ float As[BM * LDA];
    __shared__ float Bs[BN * LDA];

    const int tid  = threadIdx.x;
    const int wid  = tid >> 5;
    const int lane = tid & 31;
    const int g    = lane >> 2;
    const int t4   = lane & 3;
    const int wm   = (wid % WGM) * (BM / WGM);
    const int wn   = (wid / WGM) * (BN / WGN);
    const int bm   = blockIdx.y * BM;
    const int bn   = blockIdx.x * BN;

    float acc[MT][NT][4];
#pragma unroll
    for (int i = 0; i < MT; i++)
#pragma unroll
        for (int j = 0; j < NT; j++)
#pragma unroll
            for (int q = 0; q < 4; q++) acc[i][j][q] = 0.f;

    float4 pa[AV], pb[BV];

    // prefetch tile kk = 0
#pragma unroll
    for (int i = 0; i < AV; ++i) {
        int v   = tid + i * THREADS;
        int row = v / (BK / 4), kq = v % (BK / 4);
        pa[i] = *(const float4*)(A + (size_t)(bm + row) * K + kq * 4);
    }
#pragma unroll
    for (int i = 0; i < BV; ++i) {
        int v   = tid + i * THREADS;
        int row = v / (BK / 4), kq = v % (BK / 4);
        pb[i] = *(const float4*)(Bw + (size_t)(bn + row) * K + kq * 4);
    }

    for (int kk = 0; kk < K; kk += BK) {
        // commit prefetched tile to SMEM (RNA tf32 rounding here)
#pragma unroll
        for (int i = 0; i < AV; ++i) {
            int v   = tid + i * THREADS;
            int row = v / (BK / 4), kq = v % (BK / 4);
            float* dst = As + row * LDA + kq * 4;
            dst[0] = f2tf32f(pa[i].x); dst[1] = f2tf32f(pa[i].y);
            dst[2] = f2tf32f(pa[i].z); dst[3] = f2tf32f(pa[i].w);
        }
#pragma unroll
        for (int i = 0; i < BV; ++i) {
            int v   = tid + i * THREADS;
            int row = v / (BK / 4), kq = v % (BK / 4);
            float* dst = Bs + row * LDA + kq * 4;
            dst[0] = f2tf32f(pb[i].x); dst[1] = f2tf32f(pb[i].y);
            dst[2] = f2tf32f(pb[i].z); dst[3] = f2tf32f(pb[i].w);
        }
        __syncthreads();

        // issue LDGs for the next tile; they drain under the MMA work below
        if (kk + BK < K) {
#pragma unroll
            for (int i = 0; i < AV; ++i) {
                int v   = tid + i * THREADS;
                int row = v / (BK / 4), kq = v % (BK / 4);
                pa[i] = *(const float4*)(A + (size_t)(bm + row) * K + kk + BK + kq * 4);
            }
#pragma unroll
            for (int i = 0; i < BV; ++i) {
                int v   = tid + i * THREADS;
                int row = v / (BK / 4), kq = v % (BK / 4);
                pb[i] = *(const float4*)(Bw + (size_t)(bn + row) * K + kk + BK + kq * 4);
            }
        }

#pragma unroll
        for (int k0 = 0; k0 < BK; k0 += 8) {
            unsigned a[MT][4];
#pragma unroll
            for (int mt = 0; mt < MT; ++mt) {
                int r0 = wm + mt * 16;
                a[mt][0] = __float_as_uint(As[(r0 + g)     * LDA + k0 + t4]);
                a[mt][1] = __float_as_uint(As[(r0 + 8 + g) * LDA + k0 + t4]);
                a[mt][2] = __float_as_uint(As[(r0 + g)     * LDA + k0 + t4 + 4]);
                a[mt][3] = __float_as_uint(As[(r0 + 8 + g) * LDA + k0 + t4 + 4]);
            }
            unsigned bf[NT][2];
#pragma unroll
            for (int nt = 0; nt < NT; ++nt) {
                int r0 = wn + nt * 8;
                bf[nt][0] = __float_as_uint(Bs[(r0 + g) * LDA + k0 + t4]);
                bf[nt][1] = __float_as_uint(Bs[(r0 + g) * LDA + k0 + t4 + 4]);
            }
#pragma unroll
            for (int mt = 0; mt < MT; ++mt)
#pragma unroll
                for (int nt = 0; nt < NT; ++nt)
                    mma_tf32(acc[mt][nt], a[mt][0], a[mt][1], a[mt][2], a[mt][3],
                             bf[nt][0], bf[nt][1]);
        }
        __syncthreads();
    }

    // epilogue (+bias)
#pragma unroll
    for (int mt = 0; mt < MT; ++mt) {
        int row = bm + wm + mt * 16 + g;
#pragma unroll
        for (int nt = 0; nt < NT; ++nt) {
            int col = bn + wn + nt * 8 + 2 * t4;
            float b0 = bias[col], b1 = bias[col + 1];
            float2 v0 = make_float2(acc[mt][nt][0] + b0, acc[mt][nt][1] + b1);
            float2 v1 = make_float2(acc[mt][nt][2] + b0, acc[mt][nt][3] + b1);
            *(float2*)(C + (size_t)row * N + col)       = v0;
            *(float2*)(C + (size_t)(row + 8) * N + col) = v1;
        }
    }
}

// ---------------- GRU scan: persistent, batch-partitioned groups ----------------
// 4 groups x 32 CTAs. Group g owns batch rows [g*16, g*16+16). Only intra-group
// barriers are needed per step. Each CTA owns 16 H-columns => 48 gate rows of
// h2h_w. Weights live ENTIRELY IN REGISTERS (96 tf32 words per thread).
#define SCAN_CTAS    128
#define SCAN_THREADS 256
#define CPG          32    // CTAs per group
#define BPG          16    // batch rows per group
#define CPB          16    // H columns per CTA
#define LDH          516   // padded h stride: conflict-free fragment loads
#define RSTRIDE      52    // padded partials stride: conflict-free partial stores

#define SCAN_SMEM_FLOATS (BPG*LDH + 8*BPG*RSTRIDE + 64)

__global__ void gru_bar_init() {
    if (threadIdx.x < SCAN_CTAS) g_flags[threadIdx.x] = 0u;
}

__global__ void __launch_bounds__(SCAN_THREADS, 1)
gru_scan_kernel(const float* __restrict__ h2h_w, const float* __restrict__ h2h_b,
                float* __restrict__ rnn)
{
    extern __shared__ float sm[];
    float* hs  = sm;                      // BPG*LDH staged h (fp32)
    float* red = hs + BPG * LDH;          // 8 warps * BPG rows * RSTRIDE partials
    float* bh  = red + 8 * BPG * RSTRIDE; // 48 bias slice (padded to 64)

    const int tid  = threadIdx.x;
    const int w    = tid >> 5;
    const int lane = tid & 31;
    const int g    = lane >> 2;
    const int t4   = lane & 3;

    const int grp = blockIdx.x / CPG;
    const int cta = blockIdx.x % CPG;
    const int rb0 = grp * BPG;   // first batch row of this group
    const int c0  = cta * CPB;   // first H column owned by this CTA

    // gate-thread identity (one (batch, column) cell per thread)
    const int gb  = tid >> 4;    // batch row 0..15
    const int gc  = tid & 15;    // column-in-CTA 0..15

    // ---- one-time: weight fragments straight into registers (tf32 bits) ----
    // Warp w owns K-slice [w*64, w*64+64). For mma m16n8k8 row.col, thread
    // (g,t4) of fragment B needs rows n = nt*8+g at k = k0+t4 and k0+t4+4.
    const int kb = w * 64;
    unsigned bw[8][6][2];
#pragma unroll
    for (int nt = 0; nt < 6; ++nt) {
        int n    = nt * 8 + g;              // gate-row 0..47
        int gate = n >> 4, cl = n & 15;
        const float* wrow = h2h_w + (size_t)(gate * HDIM + c0 + cl) * HDIM + kb;
#pragma unroll
        for (int ks = 0; ks < 8; ++ks) {
            bw[ks][nt][0] = f2tf32(__ldg(wrow + ks * 8 + t4));
            bw[ks][nt][1] = f2tf32(__ldg(wrow + ks * 8 + t4 + 4));
        }
    }
    if (tid < 48) {
        int gate = tid >> 4, cl = tid & 15;
        bh[tid] = h2h_b[gate * HDIM + c0 + cl];
    }
    __syncthreads();

    unsigned* myflag = &g_flags[blockIdx.x];
    unsigned* grpflags = &g_flags[grp * CPG];

    for (int t = 0; t < T_STEPS; ++t) {
        // ---- prefetch x_proj contribution for this step (independent of h) ----
        const float* xp = g_xproj + ((size_t)t * BATCH + rb0 + gb) * G3 + c0 + gc;
        float xr = __ldcg(xp);
        float xu = __ldcg(xp + HDIM);
        float xn = __ldcg(xp + 2 * HDIM);

        // ---- stage h_t (fp32). t=0: h0 == 0. .cg bypasses possibly-stale L1. ----
        if (t == 0) {
            for (int i = tid; i < BPG * LDH; i += SCAN_THREADS) hs[i] = 0.f;
        } else {
            const float* hsrc = g_hbuf + (size_t)(t & 1) * BATCH * HDIM
                                       + (size_t)rb0 * HDIM;
#pragma unroll
            for (int i = 0; i < 8; ++i) {
                int v = tid + i * SCAN_THREADS;
                int e = v * 4;
                int b = e >> 9;            // batch row 0..15
                int k = e & (HDIM - 1);
                float4 d = __ldcg((const float4*)(hsrc + (size_t)b * HDIM + k));
                float* dst = hs + b * LDH + k;
                dst[0] = d.x; dst[1] = d.y; dst[2] = d.z; dst[3] = d.w;
            }
        }
        __syncthreads();

        // ---- z = h @ Wslice^T : M=16, N=48, K=512 split 64 per warp ----
        float acc[6][4];
#pragma unroll
        for (int nt = 0; nt < 6; ++nt) {
            acc[nt][0] = 0.f; acc[nt][1] = 0.f; acc[nt][2] = 0.f; acc[nt][3] = 0.f;
        }
#pragma unroll
        for (int ks = 0; ks < 8; ++ks) {
            int k0 = kb + ks * 8;
            unsigned a0 = f2tf32(hs[g * LDH + k0 + t4]);
            unsigned a1 = f2tf32(hs[(g + 8) * LDH + k0 + t4]);
            unsigned a2 = f2tf32(hs[g * LDH + k0 + t4 + 4]);
            unsigned a3 = f2tf32(hs[(g + 8) * LDH + k0 + t4 + 4]);
#pragma unroll
            for (int nt = 0; nt < 6; ++nt)
                mma_tf32(acc[nt], a0, a1, a2, a3, bw[ks][nt][0], bw[ks][nt][1]);
        }
        // per-warp partials -> smem (RSTRIDE padding: conflict-free)
#pragma unroll
        for (int nt = 0; nt < 6; ++nt) {
            int col = nt * 8 + 2 * t4;
            red[(w * BPG + g)     * RSTRIDE + col]     = acc[nt][0];
            red[(w * BPG + g)     * RSTRIDE + col + 1] = acc[nt][1];
            red[(w * BPG + g + 8) * RSTRIDE + col]     = acc[nt][2];
            red[(w * BPG + g + 8) * RSTRIDE + col + 1] = acc[nt][3];
        }
        __syncthreads();

        // ---- gates with folded 8-way reduction ----
        float hnew;
        {
            float zr = bh[gc], zu = bh[16 + gc], zn = bh[32 + gc];
#pragma unroll
            for (int ww = 0; ww < 8; ++ww) {
                const float* rp = red + (ww * BPG + gb) * RSTRIDE;
                zr += rp[gc];
                zu += rp[16 + gc];
                zn += rp[32 + gc];
            }
            float r  = 1.f / (1.f + __expf(-(xr + zr)));
            float u  = 1.f / (1.f + __expf(-(xu + zu)));
            float narg = xn + r * zn;
            float nn = 2.f / (1.f + __expf(-2.f * narg)) - 1.f;   // tanh
            float hold = hs[gb * LDH + c0 + gc];
            hnew = u * hold + (1.f - u) * nn;
            // publish h for the next step (this store must precede the flag)
            g_hbuf[(size_t)((t + 1) & 1) * BATCH * HDIM
                   + (size_t)(rb0 + gb) * HDIM + c0 + gc] = hnew;
        }

        if (t < T_STEPS - 1) {
            __syncthreads();   // CTA-wide: all g_hbuf stores issued & ordered
            if (tid == 0) {
                asm volatile("st.release.gpu.global.u32 [%0], %1;"
                             :: "l"(myflag), "r"((unsigned)(t + 1)) : "memory");
            }
            // rnn store is NOT needed by anyone inside the scan: overlap it
            // with the barrier wait.
            rnn[((size_t)t * BATCH + rb0 + gb) * HDIM + c0 + gc] = hnew;
            if (w == 0) {  // 32 lanes poll 32 flags in parallel
                unsigned v;
                do {
                    asm volatile("ld.acquire.gpu.global.u32 %0, [%1];"
                                 : "=r"(v) : "l"(grpflags + lane) : "memory");
                } while (v < (unsigned)(t + 1));
            }
            __syncthreads();
        } else {
            rnn[((size_t)t * BATCH + rb0 + gb) * HDIM + c0 + gc] = hnew;
        }
    }
}

// ---------------- launch ----------------
extern "C" void kernel_launch(void* const* d_in, const int* in_sizes, int n_in,
                              void* d_out, int out_size) {
    const float* x     = (const float*)d_in[0];
    const float* x2h_w = (const float*)d_in[1];
    const float* x2h_b = (const float*)d_in[2];
    const float* h2h_w = (const float*)d_in[3];
    const float* h2h_b = (const float*)d_in[4];
    const float* fc_w  = (const float*)d_in[5];
    const float* fc_b  = (const float*)d_in[6];
    float* out = (float*)d_out;

    const size_t OUT_E = (size_t)T_STEPS * BATCH * ODIM;   // 2,097,152
    const size_t RNN_E = (size_t)T_STEPS * BATCH * HDIM;   // 16,777,216

    float* xproj = nullptr;
    float* grnn  = nullptr;
    cudaGetSymbolAddress((void**)&xproj, g_xproj);
    cudaGetSymbolAddress((void**)&grnn,  g_rnn);

    // Output layout: reference returns (out, rnn_activity); handle flat concat
    // as well as single-tensor cases defensively.
    float* outp = nullptr;
    float* rnnp = grnn;
    if ((size_t)out_size >= OUT_E + RNN_E) { outp = out; rnnp = out + OUT_E; }
    else if ((size_t)out_size == RNN_E)    { rnnp = out; }
    else                                   { outp = out; }

    // 0) reset scan barrier flags (graph-replay deterministic)
    gru_bar_init<<<1, SCAN_CTAS>>>();

    // 1) x_proj = x @ x2h_w^T + x2h_b : [32768, 1536]
    {
        const int M = T_STEPS * BATCH, N = G3, K = IDIM;
        dim3 grid(N / 128, M / 128);
        gemm_tf32_nt<128, 128, 32, 2, 4><<<grid, 256>>>(x, x2h_w, x2h_b, xproj, M, N, K);
    }

    // 2) GRU scan (persistent, 128 co-resident CTAs)
    {
        static const int smem_bytes = SCAN_SMEM_FLOATS * (int)sizeof(float);
        cudaFuncSetAttribute(gru_scan_kernel,
                             cudaFuncAttributeMaxDynamicSharedMemorySize, smem_bytes);
        gru_scan_kernel<<<SCAN_CTAS, SCAN_THREADS, smem_bytes>>>(h2h_w, h2h_b, rnnp);
    }

    // 3) out = rnn @ fc_w^T + fc_b : [32768, 64]
    if (outp) {
        const int M = T_STEPS * BATCH, N = ODIM, K = HDIM;
        dim3 grid(N / 64, M / 128);
        gemm_tf32_nt<128, 64, 32, 4, 2><<<grid, 256>>>(rnnp, fc_w, fc_b, outp, M, N, K);
    }
}

// round 7
// speedup vs baseline: 1.7894x; 1.7894x over previous
#include <cuda_runtime.h>
#include <cuda_bf16.h>
#include <cstdint>

// Problem dims (fixed by the reference)
#define T_STEPS 512
#define BATCH   64
#define IDIM    256
#define HDIM    512
#define ODIM    64
#define G3      (3*HDIM)   // 1536

// ---------------- device scratch (no allocations allowed) ----------------
__device__ float    g_xproj[(size_t)T_STEPS * BATCH * G3];    // x @ x2h_w^T + b
__device__ float    g_rnn  [(size_t)T_STEPS * BATCH * HDIM];  // fallback rnn buffer
__device__ float    g_hbuf [2 * BATCH * HDIM];                // double-buffered h
__device__ unsigned g_bar  [4];                               // per-group barrier counters

// ---------------- tf32 helpers ----------------
__device__ __forceinline__ unsigned f2tf32(float x) {
    unsigned r;
    asm("cvt.rna.tf32.f32 %0, %1;" : "=r"(r) : "f"(x));
    return r;
}
__device__ __forceinline__ float f2tf32f(float x) { return __uint_as_float(f2tf32(x)); }

__device__ __forceinline__ void mma_tf32(float* c,
                                         unsigned a0, unsigned a1, unsigned a2, unsigned a3,
                                         unsigned b0, unsigned b1) {
    asm volatile(
        "mma.sync.aligned.m16n8k8.row.col.f32.tf32.tf32.f32 "
        "{%0,%1,%2,%3}, {%4,%5,%6,%7}, {%8,%9}, {%0,%1,%2,%3};\n"
        : "+f"(c[0]), "+f"(c[1]), "+f"(c[2]), "+f"(c[3])
        : "r"(a0), "r"(a1), "r"(a2), "r"(a3), "r"(b0), "r"(b1));
}

// ---------------- tf32 GEMM with register double-buffer prefetch ----------------
// C[M,N] = A[M,K] * B[N,K]^T + bias.  RNA tf32 rounding applied on SMEM store.
template <int BM, int BN, int BK, int WGM, int WGN>
__global__ void __launch_bounds__(WGM * WGN * 32)
gemm_tf32_nt(const float* __restrict__ A, const float* __restrict__ Bw,
             const float* __restrict__ bias, float* __restrict__ C,
             int M, int N, int K)
{
    constexpr int THREADS = WGM * WGN * 32;
    constexpr int MT = BM / (WGM * 16);
    constexpr int NT = BN / (WGN * 8);
    constexpr int LDA = BK + 4;                    // padded: conflict-free loads
    constexpr int AV = (BM * (BK / 4)) / THREADS;  // float4 per thread (A tile)
    constexpr int BV = (BN * (BK / 4)) / THREADS;  // float4 per thread (B tile)

    __shared__ float As[BM * LDA];
    __shared__ float Bs[BN * LDA];

    const int tid  = threadIdx.x;
    const int wid  = tid >> 5;
    const int lane = tid & 31;
    const int g    = lane >> 2;
    const int t4   = lane & 3;
    const int wm   = (wid % WGM) * (BM / WGM);
    const int wn   = (wid / WGM) * (BN / WGN);
    const int bm   = blockIdx.y * BM;
    const int bn   = blockIdx.x * BN;

    float acc[MT][NT][4];
#pragma unroll
    for (int i = 0; i < MT; i++)
#pragma unroll
        for (int j = 0; j < NT; j++)
#pragma unroll
            for (int q = 0; q < 4; q++) acc[i][j][q] = 0.f;

    float4 pa[AV], pb[BV];

    // prefetch tile kk = 0
#pragma unroll
    for (int i = 0; i < AV; ++i) {
        int v   = tid + i * THREADS;
        int row = v / (BK / 4), kq = v % (BK / 4);
        pa[i] = *(const float4*)(A + (size_t)(bm + row) * K + kq * 4);
    }
#pragma unroll
    for (int i = 0; i < BV; ++i) {
        int v   = tid + i * THREADS;
        int row = v / (BK / 4), kq = v % (BK / 4);
        pb[i] = *(const float4*)(Bw + (size_t)(bn + row) * K + kq * 4);
    }

    for (int kk = 0; kk < K; kk += BK) {
        // commit prefetched tile to SMEM (RNA tf32 rounding here)
#pragma unroll
        for (int i = 0; i < AV; ++i) {
            int v   = tid + i * THREADS;
            int row = v / (BK / 4), kq = v % (BK / 4);
            float* dst = As + row * LDA + kq * 4;
            dst[0] = f2tf32f(pa[i].x); dst[1] = f2tf32f(pa[i].y);
            dst[2] = f2tf32f(pa[i].z); dst[3] = f2tf32f(pa[i].w);
        }
#pragma unroll
        for (int i = 0; i < BV; ++i) {
            int v   = tid + i * THREADS;
            int row = v / (BK / 4), kq = v % (BK / 4);
            float* dst = Bs + row * LDA + kq * 4;
            dst[0] = f2tf32f(pb[i].x); dst[1] = f2tf32f(pb[i].y);
            dst[2] = f2tf32f(pb[i].z); dst[3] = f2tf32f(pb[i].w);
        }
        __syncthreads();

        // issue LDGs for the next tile; they drain under the MMA work below
        if (kk + BK < K) {
#pragma unroll
            for (int i = 0; i < AV; ++i) {
                int v   = tid + i * THREADS;
                int row = v / (BK / 4), kq = v % (BK / 4);
                pa[i] = *(const float4*)(A + (size_t)(bm + row) * K + kk + BK + kq * 4);
            }
#pragma unroll
            for (int i = 0; i < BV; ++i) {
                int v   = tid + i * THREADS;
                int row = v / (BK / 4), kq = v % (BK / 4);
                pb[i] = *(const float4*)(Bw + (size_t)(bn + row) * K + kk + BK + kq * 4);
            }
        }

#pragma unroll
        for (int k0 = 0; k0 < BK; k0 += 8) {
            unsigned a[MT][4];
#pragma unroll
            for (int mt = 0; mt < MT; ++mt) {
                int r0 = wm + mt * 16;
                a[mt][0] = __float_as_uint(As[(r0 + g)     * LDA + k0 + t4]);
                a[mt][1] = __float_as_uint(As[(r0 + 8 + g) * LDA + k0 + t4]);
                a[mt][2] = __float_as_uint(As[(r0 + g)     * LDA + k0 + t4 + 4]);
                a[mt][3] = __float_as_uint(As[(r0 + 8 + g) * LDA + k0 + t4 + 4]);
            }
            unsigned bf[NT][2];
#pragma unroll
            for (int nt = 0; nt < NT; ++nt) {
                int r0 = wn + nt * 8;
                bf[nt][0] = __float_as_uint(Bs[(r0 + g) * LDA + k0 + t4]);
                bf[nt][1] = __float_as_uint(Bs[(r0 + g) * LDA + k0 + t4 + 4]);
            }
#pragma unroll
            for (int mt = 0; mt < MT; ++mt)
#pragma unroll
                for (int nt = 0; nt < NT; ++nt)
                    mma_tf32(acc[mt][nt], a[mt][0], a[mt][1], a[mt][2], a[mt][3],
                             bf[nt][0], bf[nt][1]);
        }
        __syncthreads();
    }

    // epilogue (+bias)
#pragma unroll
    for (int mt = 0; mt < MT; ++mt) {
        int row = bm + wm + mt * 16 + g;
#pragma unroll
        for (int nt = 0; nt < NT; ++nt) {
            int col = bn + wn + nt * 8 + 2 * t4;
            float b0 = bias[col], b1 = bias[col + 1];
            float2 v0 = make_float2(acc[mt][nt][0] + b0, acc[mt][nt][1] + b1);
            float2 v1 = make_float2(acc[mt][nt][2] + b0, acc[mt][nt][3] + b1);
            *(float2*)(C + (size_t)row * N + col)       = v0;
            *(float2*)(C + (size_t)(row + 8) * N + col) = v1;
        }
    }
}

// ---------------- GRU scan: persistent, batch-partitioned groups ----------------
// 4 groups x 32 CTAs. Group g owns batch rows [g*16, g*16+16). Only intra-group
// barriers are needed per step. Each CTA owns 16 H-columns => 48 gate rows of
// h2h_w (r/u/n) held in SMEM as tf32.  (R4 structure — measured 1877us total.)
#define SCAN_CTAS    128
#define SCAN_THREADS 256
#define CPG          32    // CTAs per group
#define BPG          16    // batch rows per group
#define CPB          16    // H columns per CTA
#define NROWS        48    // gate rows per CTA (3 * CPB)
#define LDW          516   // padded K-stride: conflict-free fragment loads
#define RSTRIDE      52    // padded partials stride: conflict-free partial stores

#define SCAN_SMEM_FLOATS (NROWS*LDW + BPG*LDW + 8*BPG*RSTRIDE + 64)

__global__ void gru_bar_init() {
    if (threadIdx.x < 4) g_bar[threadIdx.x] = 0u;
}

__global__ void __launch_bounds__(SCAN_THREADS, 1)
gru_scan_kernel(const float* __restrict__ h2h_w, const float* __restrict__ h2h_b,
                float* __restrict__ rnn)
{
    extern __shared__ float sm[];
    float* Ws  = sm;                      // NROWS*LDW weights (tf32 bits as float)
    float* hs  = Ws + NROWS * LDW;        // BPG*LDW staged h (fp32)
    float* red = hs + BPG * LDW;          // 8 warps * BPG rows * RSTRIDE partials
    float* bh  = red + 8 * BPG * RSTRIDE; // 48 bias slice (padded to 64)

    const int tid  = threadIdx.x;
    const int w    = tid >> 5;
    const int lane = tid & 31;
    const int g    = lane >> 2;
    const int t4   = lane & 3;

    const int grp = blockIdx.x / CPG;
    const int cta = blockIdx.x % CPG;
    const int rb0 = grp * BPG;   // first batch row of this group
    const int c0  = cta * CPB;   // first H column owned by this CTA

    // gate-thread identity (one (batch, column) cell per thread)
    const int gb  = tid >> 4;    // batch row 0..15
    const int gc  = tid & 15;    // column-in-CTA 0..15

    // one-time: load weight slice (rounded to tf32) + bias slice
    for (int idx = tid; idx < NROWS * HDIM; idx += SCAN_THREADS) {
        int n = idx >> 9;            // gate-row 0..47
        int k = idx & (HDIM - 1);
        int gate = n >> 4, cl = n & 15;
        int grow = gate * HDIM + c0 + cl;
        Ws[n * LDW + k] = f2tf32f(h2h_w[(size_t)grow * HDIM + k]);
    }
    if (tid < NROWS) {
        int gate = tid >> 4, cl = tid & 15;
        bh[tid] = h2h_b[gate * HDIM + c0 + cl];
    }
    __syncthreads();

    unsigned* barp = &g_bar[grp];

    for (int t = 0; t < T_STEPS; ++t) {
        // ---- prefetch x_proj contribution for this step (independent of h) ----
        const float* xp = g_xproj + ((size_t)t * BATCH + rb0 + gb) * G3 + c0 + gc;
        float xr = __ldcg(xp);
        float xu = __ldcg(xp + HDIM);
        float xn = __ldcg(xp + 2 * HDIM);

        // ---- stage h_t (fp32). t=0: h0 == 0. .cg bypasses possibly-stale L1. ----
        if (t == 0) {
            for (int i = tid; i < BPG * LDW; i += SCAN_THREADS) hs[i] = 0.f;
        } else {
            const float* hsrc = g_hbuf + (size_t)(t & 1) * BATCH * HDIM
                                       + (size_t)rb0 * HDIM;
#pragma unroll
            for (int v = tid; v < BPG * HDIM / 4; v += SCAN_THREADS) {
                int e = v * 4;
                int b = e >> 9;            // batch row 0..15
                int k = e & (HDIM - 1);
                float4 d = __ldcg((const float4*)(hsrc + (size_t)b * HDIM + k));
                float* dst = hs + b * LDW + k;
                dst[0] = d.x; dst[1] = d.y; dst[2] = d.z; dst[3] = d.w;
            }
        }
        __syncthreads();

        // ---- z = h @ Wslice^T : M=16, N=48, K=512 split 64 per warp ----
        float acc[6][4];
#pragma unroll
        for (int nt = 0; nt < 6; ++nt) {
            acc[nt][0] = 0.f; acc[nt][1] = 0.f; acc[nt][2] = 0.f; acc[nt][3] = 0.f;
        }
        const int kb = w * 64;
#pragma unroll
        for (int ks = 0; ks < 8; ++ks) {
            int k0 = kb + ks * 8;
            unsigned a0 = f2tf32(hs[g * LDW + k0 + t4]);
            unsigned a1 = f2tf32(hs[(g + 8) * LDW + k0 + t4]);
            unsigned a2 = f2tf32(hs[g * LDW + k0 + t4 + 4]);
            unsigned a3 = f2tf32(hs[(g + 8) * LDW + k0 + t4 + 4]);
#pragma unroll
            for (int nt = 0; nt < 6; ++nt) {
                unsigned b0 = __float_as_uint(Ws[(nt * 8 + g) * LDW + k0 + t4]);
                unsigned b1 = __float_as_uint(Ws[(nt * 8 + g) * LDW + k0 + t4 + 4]);
                mma_tf32(acc[nt], a0, a1, a2, a3, b0, b1);
            }
        }
        // per-warp partials -> smem (RSTRIDE padding: conflict-free)
#pragma unroll
        for (int nt = 0; nt < 6; ++nt) {
            int col = nt * 8 + 2 * t4;
            red[(w * BPG + g)     * RSTRIDE + col]     = acc[nt][0];
            red[(w * BPG + g)     * RSTRIDE + col + 1] = acc[nt][1];
            red[(w * BPG + g + 8) * RSTRIDE + col]     = acc[nt][2];
            red[(w * BPG + g + 8) * RSTRIDE + col + 1] = acc[nt][3];
        }
        __syncthreads();

        // ---- gates with folded 8-way reduction ----
        float hnew;
        {
            float zr = bh[gc], zu = bh[16 + gc], zn = bh[32 + gc];
#pragma unroll
            for (int ww = 0; ww < 8; ++ww) {
                const float* rp = red + (ww * BPG + gb) * RSTRIDE;
                zr += rp[gc];
                zu += rp[16 + gc];
                zn += rp[32 + gc];
            }
            float r  = 1.f / (1.f + __expf(-(xr + zr)));
            float u  = 1.f / (1.f + __expf(-(xu + zu)));
            float narg = xn + r * zn;
            float nn = 2.f / (1.f + __expf(-2.f * narg)) - 1.f;   // fast tanh
            float hold = hs[gb * LDW + c0 + gc];
            hnew = u * hold + (1.f - u) * nn;
            // publish h for the next step (must be visible before the release)
            g_hbuf[(size_t)((t + 1) & 1) * BATCH * HDIM
                   + (size_t)(rb0 + gb) * HDIM + c0 + gc] = hnew;
        }

        // ---- intra-group barrier: release-add + acquire-poll ----
        if (t < T_STEPS - 1) {
            __syncthreads();   // CTA-wide ordering of the g_hbuf stores
            if (tid == 0) {
                asm volatile("red.release.gpu.global.add.u32 [%0], %1;"
                             :: "l"(barp), "r"(1u) : "memory");
            }
            // rnn store is not consumed inside the scan: overlap with the wait
            rnn[((size_t)t * BATCH + rb0 + gb) * HDIM + c0 + gc] = hnew;
            if (tid == 0) {
                unsigned target = (unsigned)(t + 1) * CPG;
                unsigned v;
                do {
                    asm volatile("ld.acquire.gpu.global.u32 %0, [%1];"
                                 : "=r"(v) : "l"(barp) : "memory");
                } while (v < target);
            }
            __syncthreads();
        } else {
            rnn[((size_t)t * BATCH + rb0 + gb) * HDIM + c0 + gc] = hnew;
        }
    }
}

// ---------------- launch ----------------
extern "C" void kernel_launch(void* const* d_in, const int* in_sizes, int n_in,
                              void* d_out, int out_size) {
    const float* x     = (const float*)d_in[0];
    const float* x2h_w = (const float*)d_in[1];
    const float* x2h_b = (const float*)d_in[2];
    const float* h2h_w = (const float*)d_in[3];
    const float* h2h_b = (const float*)d_in[4];
    const float* fc_w  = (const float*)d_in[5];
    const float* fc_b  = (const float*)d_in[6];
    float* out = (float*)d_out;

    const size_t OUT_E = (size_t)T_STEPS * BATCH * ODIM;   // 2,097,152
    const size_t RNN_E = (size_t)T_STEPS * BATCH * HDIM;   // 16,777,216

    float* xproj = nullptr;
    float* grnn  = nullptr;
    cudaGetSymbolAddress((void**)&xproj, g_xproj);
    cudaGetSymbolAddress((void**)&grnn,  g_rnn);

    // Output layout: reference returns (out, rnn_activity); handle flat concat
    // as well as single-tensor cases defensively.
    float* outp = nullptr;
    float* rnnp = grnn;
    if ((size_t)out_size >= OUT_E + RNN_E) { outp = out; rnnp = out + OUT_E; }
    else if ((size_t)out_size == RNN_E)    { rnnp = out; }
    else                                   { outp = out; }

    // 0) reset scan barrier counters (graph-replay deterministic)
    gru_bar_init<<<1, 32>>>();

    // 1) x_proj = x @ x2h_w^T + x2h_b : [32768, 1536]
    {
        const int M = T_STEPS * BATCH, N = G3, K = IDIM;
        dim3 grid(N / 128, M / 128);
        gemm_tf32_nt<128, 128, 32, 2, 4><<<grid, 256>>>(x, x2h_w, x2h_b, xproj, M, N, K);
    }

    // 2) GRU scan (persistent, 128 co-resident CTAs)
    {
        static const int smem_bytes = SCAN_SMEM_FLOATS * (int)sizeof(float);
        cudaFuncSetAttribute(gru_scan_kernel,
                             cudaFuncAttributeMaxDynamicSharedMemorySize, smem_bytes);
        gru_scan_kernel<<<SCAN_CTAS, SCAN_THREADS, smem_bytes>>>(h2h_w, h2h_b, rnnp);
    }

    // 3) out = rnn @ fc_w^T + fc_b : [32768, 64]
    if (outp) {
        const int M = T_STEPS * BATCH, N = ODIM, K = HDIM;
        dim3 grid(N / 64, M / 128);
        gemm_tf32_nt<128, 64, 32, 4, 2><<<grid, 256>>>(rnnp, fc_w, fc_b, outp, M, N, K);
    }
}

// round 8
// speedup vs baseline: 1.8659x; 1.0427x over previous
#include <cuda_runtime.h>
#include <cuda_bf16.h>
#include <cstdint>

// Problem dims (fixed by the reference)
#define T_STEPS 512
#define BATCH   64
#define IDIM    256
#define HDIM    512
#define ODIM    64
#define G3      (3*HDIM)   // 1536

// ---------------- device scratch (no allocations allowed) ----------------
__device__ float    g_xproj[(size_t)T_STEPS * BATCH * G3];    // x @ x2h_w^T + b
__device__ float    g_rnn  [(size_t)T_STEPS * BATCH * HDIM];  // fallback rnn buffer
__device__ float    g_hbuf [2 * BATCH * HDIM];                // double-buffered h
__device__ unsigned g_flags[128 * 8];                         // per-CTA flags, 32B stride

// ---------------- tf32 helpers ----------------
__device__ __forceinline__ unsigned f2tf32(float x) {
    unsigned r;
    asm("cvt.rna.tf32.f32 %0, %1;" : "=r"(r) : "f"(x));
    return r;
}
__device__ __forceinline__ float f2tf32f(float x) { return __uint_as_float(f2tf32(x)); }

__device__ __forceinline__ void mma_tf32(float* c,
                                         unsigned a0, unsigned a1, unsigned a2, unsigned a3,
                                         unsigned b0, unsigned b1) {
    asm volatile(
        "mma.sync.aligned.m16n8k8.row.col.f32.tf32.tf32.f32 "
        "{%0,%1,%2,%3}, {%4,%5,%6,%7}, {%8,%9}, {%0,%1,%2,%3};\n"
        : "+f"(c[0]), "+f"(c[1]), "+f"(c[2]), "+f"(c[3])
        : "r"(a0), "r"(a1), "r"(a2), "r"(a3), "r"(b0), "r"(b1));
}

// ---------------- tf32 GEMM with register double-buffer prefetch ----------------
// C[M,N] = A[M,K] * B[N,K]^T + bias.  RNA tf32 rounding applied on SMEM store.
template <int BM, int BN, int BK, int WGM, int WGN>
__global__ void __launch_bounds__(WGM * WGN * 32)
gemm_tf32_nt(const float* __restrict__ A, const float* __restrict__ Bw,
             const float* __restrict__ bias, float* __restrict__ C,
             int M, int N, int K)
{
    constexpr int THREADS = WGM * WGN * 32;
    constexpr int MT = BM / (WGM * 16);
    constexpr int NT = BN / (WGN * 8);
    constexpr int LDA = BK + 4;                    // padded: conflict-free loads
    constexpr int AV = (BM * (BK / 4)) / THREADS;  // float4 per thread (A tile)
    constexpr int BV = (BN * (BK / 4)) / THREADS;  // float4 per thread (B tile)

    __shared__ float As[BM * LDA];
    __shared__ float Bs[BN * LDA];

    const int tid  = threadIdx.x;
    const int wid  = tid >> 5;
    const int lane = tid & 31;
    const int g    = lane >> 2;
    const int t4   = lane & 3;
    const int wm   = (wid % WGM) * (BM / WGM);
    const int wn   = (wid / WGM) * (BN / WGN);
    const int bm   = blockIdx.y * BM;
    const int bn   = blockIdx.x * BN;

    float acc[MT][NT][4];
#pragma unroll
    for (int i = 0; i < MT; i++)
#pragma unroll
        for (int j = 0; j < NT; j++)
#pragma unroll
            for (int q = 0; q < 4; q++) acc[i][j][q] = 0.f;

    float4 pa[AV], pb[BV];

    // prefetch tile kk = 0
#pragma unroll
    for (int i = 0; i < AV; ++i) {
        int v   = tid + i * THREADS;
        int row = v / (BK / 4), kq = v % (BK / 4);
        pa[i] = *(const float4*)(A + (size_t)(bm + row) * K + kq * 4);
    }
#pragma unroll
    for (int i = 0; i < BV; ++i) {
        int v   = tid + i * THREADS;
        int row = v / (BK / 4), kq = v % (BK / 4);
        pb[i] = *(const float4*)(Bw + (size_t)(bn + row) * K + kq * 4);
    }

    for (int kk = 0; kk < K; kk += BK) {
        // commit prefetched tile to SMEM (RNA tf32 rounding here)
#pragma unroll
        for (int i = 0; i < AV; ++i) {
            int v   = tid + i * THREADS;
            int row = v / (BK / 4), kq = v % (BK / 4);
            float* dst = As + row * LDA + kq * 4;
            dst[0] = f2tf32f(pa[i].x); dst[1] = f2tf32f(pa[i].y);
            dst[2] = f2tf32f(pa[i].z); dst[3] = f2tf32f(pa[i].w);
        }
#pragma unroll
        for (int i = 0; i < BV; ++i) {
            int v   = tid + i * THREADS;
            int row = v / (BK / 4), kq = v % (BK / 4);
            float* dst = Bs + row * LDA + kq * 4;
            dst[0] = f2tf32f(pb[i].x); dst[1] = f2tf32f(pb[i].y);
            dst[2] = f2tf32f(pb[i].z); dst[3] = f2tf32f(pb[i].w);
        }
        __syncthreads();

        // issue LDGs for the next tile; they drain under the MMA work below
        if (kk + BK < K) {
#pragma unroll
            for (int i = 0; i < AV; ++i) {
                int v   = tid + i * THREADS;
                int row = v / (BK / 4), kq = v % (BK / 4);
                pa[i] = *(const float4*)(A + (size_t)(bm + row) * K + kk + BK + kq * 4);
            }
#pragma unroll
            for (int i = 0; i < BV; ++i) {
                int v   = tid + i * THREADS;
                int row = v / (BK / 4), kq = v % (BK / 4);
                pb[i] = *(const float4*)(Bw + (size_t)(bn + row) * K + kk + BK + kq * 4);
            }
        }

#pragma unroll
        for (int k0 = 0; k0 < BK; k0 += 8) {
            unsigned a[MT][4];
#pragma unroll
            for (int mt = 0; mt < MT; ++mt) {
                int r0 = wm + mt * 16;
                a[mt][0] = __float_as_uint(As[(r0 + g)     * LDA + k0 + t4]);
                a[mt][1] = __float_as_uint(As[(r0 + 8 + g) * LDA + k0 + t4]);
                a[mt][2] = __float_as_uint(As[(r0 + g)     * LDA + k0 + t4 + 4]);
                a[mt][3] = __float_as_uint(As[(r0 + 8 + g) * LDA + k0 + t4 + 4]);
            }
            unsigned bf[NT][2];
#pragma unroll
            for (int nt = 0; nt < NT; ++nt) {
                int r0 = wn + nt * 8;
                bf[nt][0] = __float_as_uint(Bs[(r0 + g) * LDA + k0 + t4]);
                bf[nt][1] = __float_as_uint(Bs[(r0 + g) * LDA + k0 + t4 + 4]);
            }
#pragma unroll
            for (int mt = 0; mt < MT; ++mt)
#pragma unroll
                for (int nt = 0; nt < NT; ++nt)
                    mma_tf32(acc[mt][nt], a[mt][0], a[mt][1], a[mt][2], a[mt][3],
                             bf[nt][0], bf[nt][1]);
        }
        __syncthreads();
    }

    // epilogue (+bias)
#pragma unroll
    for (int mt = 0; mt < MT; ++mt) {
        int row = bm + wm + mt * 16 + g;
#pragma unroll
        for (int nt = 0; nt < NT; ++nt) {
            int col = bn + wn + nt * 8 + 2 * t4;
            float b0 = bias[col], b1 = bias[col + 1];
            float2 v0 = make_float2(acc[mt][nt][0] + b0, acc[mt][nt][1] + b1);
            float2 v1 = make_float2(acc[mt][nt][2] + b0, acc[mt][nt][3] + b1);
            *(float2*)(C + (size_t)row * N + col)       = v0;
            *(float2*)(C + (size_t)(row + 8) * N + col) = v1;
        }
    }
}

// ---------------- GRU scan: persistent, batch-partitioned groups ----------------
// 4 groups x 32 CTAs. Group g owns batch rows [g*16, g*16+16). Each CTA owns
// 16 H-columns => 48 gate rows of h2h_w in SMEM (tf32).
// SYNC: per-CTA release flags; warp w waits ONLY on its 4 K-slice producers
// (CTAs 4w..4w+3 of the group), so MMA of early warps overlaps stragglers.
// Double-buffered g_hbuf is safe: a CTA reaches step t+1 (which overwrites
// buf[t&1] at its gate phase) only after ALL 32 group CTAs posted step-t flags,
// i.e. after everyone finished READING buf[t&1].
#define SCAN_CTAS    128
#define SCAN_THREADS 256
#define CPG          32    // CTAs per group
#define BPG          16    // batch rows per group
#define CPB          16    // H columns per CTA
#define NROWS        48    // gate rows per CTA (3 * CPB)
#define LDW          516   // weight K-stride: conflict-free fragment loads
#define LDH          68    // per-warp h slice row stride (16 rows x 64 cols)
#define RSTRIDE      49    // partials stride: odd*16 -> conflict-free reduce reads

#define SCAN_SMEM_FLOATS (NROWS*LDW + 8*BPG*LDH + 8*BPG*RSTRIDE + 64)

__global__ void gru_bar_init() {
    int i = blockIdx.x * blockDim.x + threadIdx.x;
    if (i < 128 * 8) g_flags[i] = 0u;
}

__global__ void __launch_bounds__(SCAN_THREADS, 1)
gru_scan_kernel(const float* __restrict__ h2h_w, const float* __restrict__ h2h_b,
                float* __restrict__ rnn)
{
    extern __shared__ float sm[];
    float* Ws  = sm;                          // NROWS*LDW weights (tf32 bits)
    float* hsA = Ws + NROWS * LDW;            // 8 warps * 16 rows * LDH h slices
    float* red = hsA + 8 * BPG * LDH;         // 8 warps * 16 rows * RSTRIDE partials
    float* bh  = red + 8 * BPG * RSTRIDE;     // 48 bias slice (padded to 64)

    const int tid  = threadIdx.x;
    const int w    = tid >> 5;
    const int lane = tid & 31;
    const int g    = lane >> 2;
    const int t4   = lane & 3;

    const int grp = blockIdx.x / CPG;
    const int cta = blockIdx.x % CPG;
    const int rb0 = grp * BPG;   // first batch row of this group
    const int c0  = cta * CPB;   // first H column owned by this CTA

    // gate-thread identity (one (batch, column) cell per thread)
    const int gb  = tid >> 4;    // batch row 0..15
    const int gc  = tid & 15;    // column-in-CTA 0..15

    float* hs = hsA + w * (BPG * LDH);   // this warp's private h slice

    // one-time: load weight slice (rounded to tf32) + bias slice
    for (int idx = tid; idx < NROWS * HDIM; idx += SCAN_THREADS) {
        int n = idx >> 9;            // gate-row 0..47
        int k = idx & (HDIM - 1);
        int gate = n >> 4, cl = n & 15;
        int grow = gate * HDIM + c0 + cl;
        Ws[n * LDW + k] = f2tf32f(h2h_w[(size_t)grow * HDIM + k]);
    }
    if (tid < NROWS) {
        int gate = tid >> 4, cl = tid & 15;
        bh[tid] = h2h_b[gate * HDIM + c0 + cl];
    }
    __syncthreads();

    unsigned* myflag = &g_flags[blockIdx.x * 8];
    // warp w waits on producers 4w..4w+3 of this group; lane polls (lane&3)
    unsigned* pflag  = &g_flags[(grp * CPG + 4 * w + (lane & 3)) * 8];

    const int kb = w * 64;   // this warp's K-slice base

    for (int t = 0; t < T_STEPS; ++t) {
        // ---- early loads: x_proj (DRAM) + hold (self-produced columns, L2) ----
        const float* xp = g_xproj + ((size_t)t * BATCH + rb0 + gb) * G3 + c0 + gc;
        float xr = __ldcg(xp);
        float xu = __ldcg(xp + HDIM);
        float xn = __ldcg(xp + 2 * HDIM);
        float hold = 0.f;
        const float* bufc = g_hbuf + (size_t)(t & 1) * BATCH * HDIM;
        if (t > 0)
            hold = __ldcg(bufc + (size_t)(rb0 + gb) * HDIM + c0 + gc);

        // ---- per-warp producer wait + stage own 16x64 h slice ----
        if (t == 0) {
#pragma unroll
            for (int i = 0; i < BPG * LDH / 32; ++i) hs[lane + 32 * i] = 0.f;
            __syncwarp();
        } else {
            // poll the 4 producer flags for this warp's K-slice
            unsigned v;
            do {
                asm volatile("ld.acquire.gpu.global.u32 %0, [%1];"
                             : "=r"(v) : "l"(pflag) : "memory");
            } while (!__all_sync(0xffffffffu, v >= (unsigned)t));

            const float* src = bufc + (size_t)rb0 * HDIM + kb;
#pragma unroll
            for (int i = 0; i < 8; ++i) {
                int idx = lane + 32 * i;     // 0..255
                int row = idx >> 4;          // 0..15
                int seg = idx & 15;          // 0..15 (16B chunks)
                float4 d = __ldcg((const float4*)(src + (size_t)row * HDIM + seg * 4));
                float* dst = hs + row * LDH + seg * 4;
                dst[0] = d.x; dst[1] = d.y; dst[2] = d.z; dst[3] = d.w;
            }
            __syncwarp();
        }

        // ---- z = h @ Wslice^T : M=16, N=48, K=512 split 64 per warp ----
        float acc[6][4];
#pragma unroll
        for (int nt = 0; nt < 6; ++nt) {
            acc[nt][0] = 0.f; acc[nt][1] = 0.f; acc[nt][2] = 0.f; acc[nt][3] = 0.f;
        }
#pragma unroll
        for (int ks = 0; ks < 8; ++ks) {
            int kl = ks * 8;          // k offset within the warp's slice
            int k0 = kb + kl;         // k offset within full H (for weights)
            unsigned a0 = f2tf32(hs[g * LDH + kl + t4]);
            unsigned a1 = f2tf32(hs[(g + 8) * LDH + kl + t4]);
            unsigned a2 = f2tf32(hs[g * LDH + kl + t4 + 4]);
            unsigned a3 = f2tf32(hs[(g + 8) * LDH + kl + t4 + 4]);
#pragma unroll
            for (int nt = 0; nt < 6; ++nt) {
                unsigned b0 = __float_as_uint(Ws[(nt * 8 + g) * LDW + k0 + t4]);
                unsigned b1 = __float_as_uint(Ws[(nt * 8 + g) * LDW + k0 + t4 + 4]);
                mma_tf32(acc[nt], a0, a1, a2, a3, b0, b1);
            }
        }
        // per-warp partials -> smem
#pragma unroll
        for (int nt = 0; nt < 6; ++nt) {
            int col = nt * 8 + 2 * t4;
            red[(w * BPG + g)     * RSTRIDE + col]     = acc[nt][0];
            red[(w * BPG + g)     * RSTRIDE + col + 1] = acc[nt][1];
            red[(w * BPG + g + 8) * RSTRIDE + col]     = acc[nt][2];
            red[(w * BPG + g + 8) * RSTRIDE + col + 1] = acc[nt][3];
        }
        __syncthreads();

        // ---- gates with folded 8-way reduction ----
        float hnew;
        {
            float zr = bh[gc], zu = bh[16 + gc], zn = bh[32 + gc];
#pragma unroll
            for (int ww = 0; ww < 8; ++ww) {
                const float* rp = red + (ww * BPG + gb) * RSTRIDE;
                zr += rp[gc];
                zu += rp[16 + gc];
                zn += rp[32 + gc];
            }
            float r  = 1.f / (1.f + __expf(-(xr + zr)));
            float u  = 1.f / (1.f + __expf(-(xu + zu)));
            float narg = xn + r * zn;
            float nn = 2.f / (1.f + __expf(-2.f * narg)) - 1.f;   // fast tanh
            hnew = u * hold + (1.f - u) * nn;
            // publish h for the next step (must precede the flag release)
            g_hbuf[(size_t)((t + 1) & 1) * BATCH * HDIM
                   + (size_t)(rb0 + gb) * HDIM + c0 + gc] = hnew;
        }

        if (t < T_STEPS - 1) {
            __syncthreads();   // all h stores of this CTA issued & ordered
            if (tid == 0) {
                asm volatile("st.release.gpu.global.u32 [%0], %1;"
                             :: "l"(myflag), "r"((unsigned)(t + 1)) : "memory");
            }
        }
        // rnn store fully off the critical path (after flag post)
        rnn[((size_t)t * BATCH + rb0 + gb) * HDIM + c0 + gc] = hnew;
    }
}

// ---------------- launch ----------------
extern "C" void kernel_launch(void* const* d_in, const int* in_sizes, int n_in,
                              void* d_out, int out_size) {
    const float* x     = (const float*)d_in[0];
    const float* x2h_w = (const float*)d_in[1];
    const float* x2h_b = (const float*)d_in[2];
    const float* h2h_w = (const float*)d_in[3];
    const float* h2h_b = (const float*)d_in[4];
    const float* fc_w  = (const float*)d_in[5];
    const float* fc_b  = (const float*)d_in[6];
    float* out = (float*)d_out;

    const size_t OUT_E = (size_t)T_STEPS * BATCH * ODIM;   // 2,097,152
    const size_t RNN_E = (size_t)T_STEPS * BATCH * HDIM;   // 16,777,216

    float* xproj = nullptr;
    float* grnn  = nullptr;
    cudaGetSymbolAddress((void**)&xproj, g_xproj);
    cudaGetSymbolAddress((void**)&grnn,  g_rnn);

    // Output layout: reference returns (out, rnn_activity); handle flat concat
    // as well as single-tensor cases defensively.
    float* outp = nullptr;
    float* rnnp = grnn;
    if ((size_t)out_size >= OUT_E + RNN_E) { outp = out; rnnp = out + OUT_E; }
    else if ((size_t)out_size == RNN_E)    { rnnp = out; }
    else                                   { outp = out; }

    // 0) reset scan flags (graph-replay deterministic)
    gru_bar_init<<<1, 1024>>>();

    // 1) x_proj = x @ x2h_w^T + x2h_b : [32768, 1536]
    {
        const int M = T_STEPS * BATCH, N = G3, K = IDIM;
        dim3 grid(N / 128, M / 128);
        gemm_tf32_nt<128, 128, 32, 2, 4><<<grid, 256>>>(x, x2h_w, x2h_b, xproj, M, N, K);
    }

    // 2) GRU scan (persistent, 128 co-resident CTAs)
    {
        static const int smem_bytes = SCAN_SMEM_FLOATS * (int)sizeof(float);
        cudaFuncSetAttribute(gru_scan_kernel,
                             cudaFuncAttributeMaxDynamicSharedMemorySize, smem_bytes);
        gru_scan_kernel<<<SCAN_CTAS, SCAN_THREADS, smem_bytes>>>(h2h_w, h2h_b, rnnp);
    }

    // 3) out = rnn @ fc_w^T + fc_b : [32768, 64]
    if (outp) {
        const int M = T_STEPS * BATCH, N = ODIM, K = HDIM;
        dim3 grid(N / 64, M / 128);
        gemm_tf32_nt<128, 64, 32, 4, 2><<<grid, 256>>>(rnnp, fc_w, fc_b, outp, M, N, K);
    }
}

// round 9
// speedup vs baseline: 1.9622x; 1.0516x over previous
#include <cuda_runtime.h>
#include <cuda_bf16.h>
#include <cstdint>

// Problem dims (fixed by the reference)
#define T_STEPS 512
#define BATCH   64
#define IDIM    256
#define HDIM    512
#define ODIM    64
#define G3      (3*HDIM)   // 1536

// ---------------- device scratch (no allocations allowed) ----------------
__device__ float    g_xproj[(size_t)T_STEPS * BATCH * G3];    // x @ x2h_w^T + b
__device__ float    g_rnn  [(size_t)T_STEPS * BATCH * HDIM];  // fallback rnn buffer
__device__ float    g_hbuf [2 * BATCH * HDIM];                // double-buffered h
__device__ unsigned g_flags[128 * 8];                         // per-CTA flags, 32B stride

// ---------------- tf32 helpers ----------------
__device__ __forceinline__ unsigned f2tf32(float x) {
    unsigned r;
    asm("cvt.rna.tf32.f32 %0, %1;" : "=r"(r) : "f"(x));
    return r;
}
__device__ __forceinline__ float f2tf32f(float x) { return __uint_as_float(f2tf32(x)); }

__device__ __forceinline__ void mma_tf32(float* c,
                                         unsigned a0, unsigned a1, unsigned a2, unsigned a3,
                                         unsigned b0, unsigned b1) {
    asm volatile(
        "mma.sync.aligned.m16n8k8.row.col.f32.tf32.tf32.f32 "
        "{%0,%1,%2,%3}, {%4,%5,%6,%7}, {%8,%9}, {%0,%1,%2,%3};\n"
        : "+f"(c[0]), "+f"(c[1]), "+f"(c[2]), "+f"(c[3])
        : "r"(a0), "r"(a1), "r"(a2), "r"(a3), "r"(b0), "r"(b1));
}

// ---------------- tf32 GEMM with register double-buffer prefetch ----------------
// C[M,N] = A[M,K] * B[N,K]^T + bias.  RNA tf32 rounding applied on SMEM store.
template <int BM, int BN, int BK, int WGM, int WGN>
__global__ void __launch_bounds__(WGM * WGN * 32)
gemm_tf32_nt(const float* __restrict__ A, const float* __restrict__ Bw,
             const float* __restrict__ bias, float* __restrict__ C,
             int M, int N, int K)
{
    constexpr int THREADS = WGM * WGN * 32;
    constexpr int MT = BM / (WGM * 16);
    constexpr int NT = BN / (WGN * 8);
    constexpr int LDA = BK + 4;                    // padded: conflict-free loads
    constexpr int AV = (BM * (BK / 4)) / THREADS;  // float4 per thread (A tile)
    constexpr int BV = (BN * (BK / 4)) / THREADS;  // float4 per thread (B tile)

    __shared__ float As[BM * LDA];
    __shared__ float Bs[BN * LDA];

    const int tid  = threadIdx.x;
    const int wid  = tid >> 5;
    const int lane = tid & 31;
    const int g    = lane >> 2;
    const int t4   = lane & 3;
    const int wm   = (wid % WGM) * (BM / WGM);
    const int wn   = (wid / WGM) * (BN / WGN);
    const int bm   = blockIdx.y * BM;
    const int bn   = blockIdx.x * BN;

    float acc[MT][NT][4];
#pragma unroll
    for (int i = 0; i < MT; i++)
#pragma unroll
        for (int j = 0; j < NT; j++)
#pragma unroll
            for (int q = 0; q < 4; q++) acc[i][j][q] = 0.f;

    float4 pa[AV], pb[BV];

    // prefetch tile kk = 0
#pragma unroll
    for (int i = 0; i < AV; ++i) {
        int v   = tid + i * THREADS;
        int row = v / (BK / 4), kq = v % (BK / 4);
        pa[i] = *(const float4*)(A + (size_t)(bm + row) * K + kq * 4);
    }
#pragma unroll
    for (int i = 0; i < BV; ++i) {
        int v   = tid + i * THREADS;
        int row = v / (BK / 4), kq = v % (BK / 4);
        pb[i] = *(const float4*)(Bw + (size_t)(bn + row) * K + kq * 4);
    }

    for (int kk = 0; kk < K; kk += BK) {
        // commit prefetched tile to SMEM (RNA tf32 rounding here)
#pragma unroll
        for (int i = 0; i < AV; ++i) {
            int v   = tid + i * THREADS;
            int row = v / (BK / 4), kq = v % (BK / 4);
            float* dst = As + row * LDA + kq * 4;
            dst[0] = f2tf32f(pa[i].x); dst[1] = f2tf32f(pa[i].y);
            dst[2] = f2tf32f(pa[i].z); dst[3] = f2tf32f(pa[i].w);
        }
#pragma unroll
        for (int i = 0; i < BV; ++i) {
            int v   = tid + i * THREADS;
            int row = v / (BK / 4), kq = v % (BK / 4);
            float* dst = Bs + row * LDA + kq * 4;
            dst[0] = f2tf32f(pb[i].x); dst[1] = f2tf32f(pb[i].y);
            dst[2] = f2tf32f(pb[i].z); dst[3] = f2tf32f(pb[i].w);
        }
        __syncthreads();

        // issue LDGs for the next tile; they drain under the MMA work below
        if (kk + BK < K) {
#pragma unroll
            for (int i = 0; i < AV; ++i) {
                int v   = tid + i * THREADS;
                int row = v / (BK / 4), kq = v % (BK / 4);
                pa[i] = *(const float4*)(A + (size_t)(bm + row) * K + kk + BK + kq * 4);
            }
#pragma unroll
            for (int i = 0; i < BV; ++i) {
                int v   = tid + i * THREADS;
                int row = v / (BK / 4), kq = v % (BK / 4);
                pb[i] = *(const float4*)(Bw + (size_t)(bn + row) * K + kk + BK + kq * 4);
            }
        }

#pragma unroll
        for (int k0 = 0; k0 < BK; k0 += 8) {
            unsigned a[MT][4];
#pragma unroll
            for (int mt = 0; mt < MT; ++mt) {
                int r0 = wm + mt * 16;
                a[mt][0] = __float_as_uint(As[(r0 + g)     * LDA + k0 + t4]);
                a[mt][1] = __float_as_uint(As[(r0 + 8 + g) * LDA + k0 + t4]);
                a[mt][2] = __float_as_uint(As[(r0 + g)     * LDA + k0 + t4 + 4]);
                a[mt][3] = __float_as_uint(As[(r0 + 8 + g) * LDA + k0 + t4 + 4]);
            }
            unsigned bf[NT][2];
#pragma unroll
            for (int nt = 0; nt < NT; ++nt) {
                int r0 = wn + nt * 8;
                bf[nt][0] = __float_as_uint(Bs[(r0 + g) * LDA + k0 + t4]);
                bf[nt][1] = __float_as_uint(Bs[(r0 + g) * LDA + k0 + t4 + 4]);
            }
#pragma unroll
            for (int mt = 0; mt < MT; ++mt)
#pragma unroll
                for (int nt = 0; nt < NT; ++nt)
                    mma_tf32(acc[mt][nt], a[mt][0], a[mt][1], a[mt][2], a[mt][3],
                             bf[nt][0], bf[nt][1]);
        }
        __syncthreads();
    }

    // epilogue (+bias)
#pragma unroll
    for (int mt = 0; mt < MT; ++mt) {
        int row = bm + wm + mt * 16 + g;
#pragma unroll
        for (int nt = 0; nt < NT; ++nt) {
            int col = bn + wn + nt * 8 + 2 * t4;
            float b0 = bias[col], b1 = bias[col + 1];
            float2 v0 = make_float2(acc[mt][nt][0] + b0, acc[mt][nt][1] + b1);
            float2 v1 = make_float2(acc[mt][nt][2] + b0, acc[mt][nt][3] + b1);
            *(float2*)(C + (size_t)row * N + col)       = v0;
            *(float2*)(C + (size_t)(row + 8) * N + col) = v1;
        }
    }
}

// ---------------- GRU scan: persistent, batch-partitioned groups ----------------
// 4 groups x 32 CTAs. Group g owns batch rows [g*16, g*16+16). Each CTA owns
// 16 H-columns => 48 gate rows of h2h_w.
// THIS ROUND: B (weight) fragments live in REGISTERS (96 tf32 words/thread,
// loaded once) — deletes 96 LDS/warp/step of SMEM crossbar traffic.
// SYNC (unchanged from R7): per-CTA release flags; warp w waits only on its 4
// K-slice producers (CTAs 4w..4w+3 of the group).
#define SCAN_CTAS    128
#define SCAN_THREADS 256
#define CPG          32    // CTAs per group
#define BPG          16    // batch rows per group
#define CPB          16    // H columns per CTA
#define NROWS        48    // gate rows per CTA (3 * CPB)
#define LDH          68    // per-warp h slice row stride (16 rows x 64 cols)
#define RSTRIDE      49    // partials stride: odd*16 -> conflict-free reduce reads

#define SCAN_SMEM_FLOATS (8*BPG*LDH + 8*BPG*RSTRIDE + 64)

__global__ void gru_bar_init() {
    int i = blockIdx.x * blockDim.x + threadIdx.x;
    if (i < 128 * 8) g_flags[i] = 0u;
}

__global__ void __launch_bounds__(SCAN_THREADS, 1)
gru_scan_kernel(const float* __restrict__ h2h_w, const float* __restrict__ h2h_b,
                float* __restrict__ rnn)
{
    extern __shared__ float sm[];
    float* hsA = sm;                          // 8 warps * 16 rows * LDH h slices
    float* red = hsA + 8 * BPG * LDH;         // 8 warps * 16 rows * RSTRIDE partials
    float* bh  = red + 8 * BPG * RSTRIDE;     // 48 bias slice (padded to 64)

    const int tid  = threadIdx.x;
    const int w    = tid >> 5;
    const int lane = tid & 31;
    const int g    = lane >> 2;
    const int t4   = lane & 3;

    const int grp = blockIdx.x / CPG;
    const int cta = blockIdx.x % CPG;
    const int rb0 = grp * BPG;   // first batch row of this group
    const int c0  = cta * CPB;   // first H column owned by this CTA

    // gate-thread identity (one (batch, column) cell per thread)
    const int gb  = tid >> 4;    // batch row 0..15
    const int gc  = tid & 15;    // column-in-CTA 0..15

    float* hs = hsA + w * (BPG * LDH);   // this warp's private h slice

    const int kb = w * 64;   // this warp's K-slice base

    // ---- one-time: weight fragments into registers (tf32 bits) ----
    // Warp w owns K-slice [kb, kb+64). For mma m16n8k8 row.col, thread (g,t4)
    // of fragment B holds rows n = nt*8+g at k = kb+ks*8+t4 and +4.
    unsigned bw[8][6][2];
#pragma unroll
    for (int nt = 0; nt < 6; ++nt) {
        int n    = nt * 8 + g;              // gate-row 0..47
        int gate = n >> 4, cl = n & 15;
        const float* wrow = h2h_w + (size_t)(gate * HDIM + c0 + cl) * HDIM + kb;
#pragma unroll
        for (int ks = 0; ks < 8; ++ks) {
            bw[ks][nt][0] = f2tf32(__ldg(wrow + ks * 8 + t4));
            bw[ks][nt][1] = f2tf32(__ldg(wrow + ks * 8 + t4 + 4));
        }
    }
    if (tid < NROWS) {
        int gate = tid >> 4, cl = tid & 15;
        bh[tid] = h2h_b[gate * HDIM + c0 + cl];
    }
    __syncthreads();

    unsigned* myflag = &g_flags[blockIdx.x * 8];
    // warp w waits on producers 4w..4w+3 of this group; lane polls (lane&3)
    unsigned* pflag  = &g_flags[(grp * CPG + 4 * w + (lane & 3)) * 8];

    for (int t = 0; t < T_STEPS; ++t) {
        // ---- early loads: x_proj (DRAM) + hold (self-produced columns, L2) ----
        const float* xp = g_xproj + ((size_t)t * BATCH + rb0 + gb) * G3 + c0 + gc;
        float xr = __ldcg(xp);
        float xu = __ldcg(xp + HDIM);
        float xn = __ldcg(xp + 2 * HDIM);
        float hold = 0.f;
        const float* bufc = g_hbuf + (size_t)(t & 1) * BATCH * HDIM;
        if (t > 0)
            hold = __ldcg(bufc + (size_t)(rb0 + gb) * HDIM + c0 + gc);

        // ---- per-warp producer wait + stage own 16x64 h slice ----
        if (t == 0) {
#pragma unroll
            for (int i = 0; i < BPG * LDH / 32; ++i) hs[lane + 32 * i] = 0.f;
            __syncwarp();
        } else {
            // poll the 4 producer flags for this warp's K-slice
            unsigned v;
            do {
                asm volatile("ld.acquire.gpu.global.u32 %0, [%1];"
                             : "=r"(v) : "l"(pflag) : "memory");
            } while (!__all_sync(0xffffffffu, v >= (unsigned)t));

            const float* src = bufc + (size_t)rb0 * HDIM + kb;
#pragma unroll
            for (int i = 0; i < 8; ++i) {
                int idx = lane + 32 * i;     // 0..255
                int row = idx >> 4;          // 0..15
                int seg = idx & 15;          // 0..15 (16B chunks)
                float4 d = __ldcg((const float4*)(src + (size_t)row * HDIM + seg * 4));
                float* dst = hs + row * LDH + seg * 4;
                dst[0] = d.x; dst[1] = d.y; dst[2] = d.z; dst[3] = d.w;
            }
            __syncwarp();
        }

        // ---- z = h @ Wslice^T : M=16, N=48, K=512 split 64 per warp ----
        float acc[6][4];
#pragma unroll
        for (int nt = 0; nt < 6; ++nt) {
            acc[nt][0] = 0.f; acc[nt][1] = 0.f; acc[nt][2] = 0.f; acc[nt][3] = 0.f;
        }
#pragma unroll
        for (int ks = 0; ks < 8; ++ks) {
            int kl = ks * 8;          // k offset within the warp's slice
            unsigned a0 = f2tf32(hs[g * LDH + kl + t4]);
            unsigned a1 = f2tf32(hs[(g + 8) * LDH + kl + t4]);
            unsigned a2 = f2tf32(hs[g * LDH + kl + t4 + 4]);
            unsigned a3 = f2tf32(hs[(g + 8) * LDH + kl + t4 + 4]);
#pragma unroll
            for (int nt = 0; nt < 6; ++nt)
                mma_tf32(acc[nt], a0, a1, a2, a3, bw[ks][nt][0], bw[ks][nt][1]);
        }
        // per-warp partials -> smem
#pragma unroll
        for (int nt = 0; nt < 6; ++nt) {
            int col = nt * 8 + 2 * t4;
            red[(w * BPG + g)     * RSTRIDE + col]     = acc[nt][0];
            red[(w * BPG + g)     * RSTRIDE + col + 1] = acc[nt][1];
            red[(w * BPG + g + 8) * RSTRIDE + col]     = acc[nt][2];
            red[(w * BPG + g + 8) * RSTRIDE + col + 1] = acc[nt][3];
        }
        __syncthreads();

        // ---- gates with folded 8-way reduction ----
        float hnew;
        {
            float zr = bh[gc], zu = bh[16 + gc], zn = bh[32 + gc];
#pragma unroll
            for (int ww = 0; ww < 8; ++ww) {
                const float* rp = red + (ww * BPG + gb) * RSTRIDE;
                zr += rp[gc];
                zu += rp[16 + gc];
                zn += rp[32 + gc];
            }
            float r  = 1.f / (1.f + __expf(-(xr + zr)));
            float u  = 1.f / (1.f + __expf(-(xu + zu)));
            float narg = xn + r * zn;
            float nn = 2.f / (1.f + __expf(-2.f * narg)) - 1.f;   // fast tanh
            hnew = u * hold + (1.f - u) * nn;
            // publish h for the next step (must precede the flag release)
            g_hbuf[(size_t)((t + 1) & 1) * BATCH * HDIM
                   + (size_t)(rb0 + gb) * HDIM + c0 + gc] = hnew;
        }

        if (t < T_STEPS - 1) {
            __syncthreads();   // all h stores of this CTA issued & ordered
            if (tid == 0) {
                asm volatile("st.release.gpu.global.u32 [%0], %1;"
                             :: "l"(myflag), "r"((unsigned)(t + 1)) : "memory");
            }
        }
        // rnn store fully off the critical path (after flag post)
        rnn[((size_t)t * BATCH + rb0 + gb) * HDIM + c0 + gc] = hnew;
    }
}

// ---------------- launch ----------------
extern "C" void kernel_launch(void* const* d_in, const int* in_sizes, int n_in,
                              void* d_out, int out_size) {
    const float* x     = (const float*)d_in[0];
    const float* x2h_w = (const float*)d_in[1];
    const float* x2h_b = (const float*)d_in[2];
    const float* h2h_w = (const float*)d_in[3];
    const float* h2h_b = (const float*)d_in[4];
    const float* fc_w  = (const float*)d_in[5];
    const float* fc_b  = (const float*)d_in[6];
    float* out = (float*)d_out;

    const size_t OUT_E = (size_t)T_STEPS * BATCH * ODIM;   // 2,097,152
    const size_t RNN_E = (size_t)T_STEPS * BATCH * HDIM;   // 16,777,216

    float* xproj = nullptr;
    float* grnn  = nullptr;
    cudaGetSymbolAddress((void**)&xproj, g_xproj);
    cudaGetSymbolAddress((void**)&grnn,  g_rnn);

    // Output layout: reference returns (out, rnn_activity); handle flat concat
    // as well as single-tensor cases defensively.
    float* outp = nullptr;
    float* rnnp = grnn;
    if ((size_t)out_size >= OUT_E + RNN_E) { outp = out; rnnp = out + OUT_E; }
    else if ((size_t)out_size == RNN_E)    { rnnp = out; }
    else                                   { outp = out; }

    // 0) reset scan flags (graph-replay deterministic)
    gru_bar_init<<<1, 1024>>>();

    // 1) x_proj = x @ x2h_w^T + x2h_b : [32768, 1536]
    {
        const int M = T_STEPS * BATCH, N = G3, K = IDIM;
        dim3 grid(N / 128, M / 128);
        gemm_tf32_nt<128, 128, 32, 2, 4><<<grid, 256>>>(x, x2h_w, x2h_b, xproj, M, N, K);
    }

    // 2) GRU scan (persistent, 128 co-resident CTAs)
    {
        static const int smem_bytes = SCAN_SMEM_FLOATS * (int)sizeof(float);
        cudaFuncSetAttribute(gru_scan_kernel,
                             cudaFuncAttributeMaxDynamicSharedMemorySize, smem_bytes);
        gru_scan_kernel<<<SCAN_CTAS, SCAN_THREADS, smem_bytes>>>(h2h_w, h2h_b, rnnp);
    }

    // 3) out = rnn @ fc_w^T + fc_b : [32768, 64]
    if (outp) {
        const int M = T_STEPS * BATCH, N = ODIM, K = HDIM;
        dim3 grid(N / 64, M / 128);
        gemm_tf32_nt<128, 64, 32, 4, 2><<<grid, 256>>>(rnnp, fc_w, fc_b, outp, M, N, K);
    }
}